// round 4
// baseline (speedup 1.0000x reference)
#include <cuda_runtime.h>
#include <cstdint>

#define NUM_IN 25   // 2*(8+2)+4+1
#define NUM_OUT 20  // 2*8+4
#define J_STRIDE 28 // layer-1 transposed row stride (floats), 16B-aligned
#define J_PAIRS 13  // 25 rows -> 13 f32x2 pairs (last half padded)
#define I_PAIRS 10  // 20 rows -> 10 pairs exactly

typedef unsigned long long u64;

__device__ __forceinline__ u64 pk2s(float v) {       // splat {v, v}
    u64 r;
    asm("mov.b64 %0, {%1, %1};" : "=l"(r) : "f"(v));
    return r;
}
__device__ __forceinline__ void upk2(u64 v, float& lo, float& hi) {
    asm("mov.b64 {%0, %1}, %2;" : "=f"(lo), "=f"(hi) : "l"(v));
}
__device__ __forceinline__ u64 ffma2(u64 a, u64 b, u64 c) {
    u64 d;
    asm("fma.rn.f32x2 %0, %1, %2, %3;" : "=l"(d) : "l"(a), "l"(b), "l"(c));
    return d;
}

// Shared layout (floats), all segments 16B-aligned:
//   sW1T: k=0..24, rows of 28 (j 0..24 real, 25..27 zero)  [0, 700)
//   sB1 : 28 (0..24 real)                                  [700, 728)
//   sW2T: k=0..24, rows of 20                              [728, 1228)
//   sB2 : 20                                               [1228, 1248)
#define OFF_W1T 0
#define OFF_B1  700
#define OFF_W2T 728
#define OFF_B2  1228
#define SMEM_FLOATS 1248

__global__ void __launch_bounds__(128, 5)
edge_mlp_kernel(const float* __restrict__ r,
                const float* __restrict__ a_data,
                const float* __restrict__ a_material,
                const float* __restrict__ a_influx,
                const float* __restrict__ b_data,
                const float* __restrict__ b_material,
                const float* __restrict__ b_influx,
                const float* __restrict__ e_data,
                const float* __restrict__ W1,
                const float* __restrict__ b1,
                const float* __restrict__ W2,
                const float* __restrict__ b2,
                float* __restrict__ out,
                int E)
{
    __shared__ __align__(16) float sAll[SMEM_FLOATS];

    // ---- Cooperative transpose-load of weights into shared ----
    for (int i = threadIdx.x; i < 25 * J_STRIDE; i += blockDim.x) {
        int k = i / J_STRIDE, j = i % J_STRIDE;
        sAll[OFF_W1T + i] = (j < NUM_IN) ? W1[j * NUM_IN + k] : 0.0f;
    }
    for (int i = threadIdx.x; i < 25 * NUM_OUT; i += blockDim.x) {
        int k = i / NUM_OUT, jj = i % NUM_OUT;
        sAll[OFF_W2T + i] = W2[jj * NUM_IN + k];
    }
    if (threadIdx.x < J_STRIDE)
        sAll[OFF_B1 + threadIdx.x] = (threadIdx.x < NUM_IN) ? b1[threadIdx.x] : 0.0f;
    if (threadIdx.x < NUM_OUT)
        sAll[OFF_B2 + threadIdx.x] = b2[threadIdx.x];

    long e = (long)blockIdx.x * blockDim.x + threadIdx.x;
    bool active = (e < E);
    long ee = active ? e : 0;

    // ---- Gather this edge's 25 inputs ----
    const float4* ad4 = reinterpret_cast<const float4*>(a_data);
    const float4* bd4 = reinterpret_cast<const float4*>(b_data);
    const float4* ed4 = reinterpret_cast<const float4*>(e_data);

    float x[NUM_IN];
    x[0] = r[ee];
    {
        float4 p = ad4[2 * ee];
        x[1] = p.x; x[2] = p.y; x[3] = p.z; x[4] = p.w;
        p = ad4[2 * ee + 1];
        x[5] = p.x; x[6] = p.y; x[7] = p.z; x[8] = p.w;
    }
    x[9]  = a_material[ee];
    x[10] = a_influx[ee];
    {
        float4 p = bd4[2 * ee];
        x[11] = p.x; x[12] = p.y; x[13] = p.z; x[14] = p.w;
        p = bd4[2 * ee + 1];
        x[15] = p.x; x[16] = p.y; x[17] = p.z; x[18] = p.w;
    }
    x[19] = b_material[ee];
    x[20] = b_influx[ee];
    {
        float4 p = ed4[ee];
        x[21] = p.x; x[22] = p.y; x[23] = p.z; x[24] = p.w;
    }

    __syncthreads();

    // ---- Layer 1: 13 packed row-pair accumulators, LDS.128 weights ----
    u64 acc[J_PAIRS + 1];   // +1 scratch for the padded pair
    {
        const ulonglong2* b1p = reinterpret_cast<const ulonglong2*>(sAll + OFF_B1);
        #pragma unroll
        for (int p = 0; p < 7; p++) {
            ulonglong2 b = b1p[p];
            acc[2 * p] = b.x;
            if (2 * p + 1 < J_PAIRS) acc[2 * p + 1] = b.y;
        }
    }
    #pragma unroll
    for (int k = 0; k < NUM_IN; k++) {
        const ulonglong2* wrow =
            reinterpret_cast<const ulonglong2*>(sAll + OFF_W1T + k * J_STRIDE);
        u64 xk = pk2s(x[k]);
        #pragma unroll
        for (int p = 0; p < 7; p++) {
            ulonglong2 w = wrow[p];
            acc[2 * p] = ffma2(w.x, xk, acc[2 * p]);
            if (2 * p + 1 < J_PAIRS) acc[2 * p + 1] = ffma2(w.y, xk, acc[2 * p + 1]);
        }
    }

    float y[2 * J_PAIRS];
    #pragma unroll
    for (int p = 0; p < J_PAIRS; p++) {
        float lo, hi;
        upk2(acc[p], lo, hi);
        y[2 * p]     = fmaxf(lo, 0.0f);
        y[2 * p + 1] = fmaxf(hi, 0.0f);
    }

    // ---- Layer 2: 10 packed accumulators, LDS.128 weights ----
    u64 z[I_PAIRS];
    {
        const ulonglong2* b2p = reinterpret_cast<const ulonglong2*>(sAll + OFF_B2);
        #pragma unroll
        for (int p = 0; p < 5; p++) {
            ulonglong2 b = b2p[p];
            z[2 * p]     = b.x;
            z[2 * p + 1] = b.y;
        }
    }
    #pragma unroll
    for (int k = 0; k < NUM_IN; k++) {
        const ulonglong2* wrow =
            reinterpret_cast<const ulonglong2*>(sAll + OFF_W2T + k * NUM_OUT);
        u64 yk = pk2s(y[k]);
        #pragma unroll
        for (int p = 0; p < 5; p++) {
            ulonglong2 w = wrow[p];
            z[2 * p]     = ffma2(w.x, yk, z[2 * p]);
            z[2 * p + 1] = ffma2(w.y, yk, z[2 * p + 1]);
        }
    }

    if (!active) return;

    float zz[NUM_OUT];
    #pragma unroll
    for (int p = 0; p < I_PAIRS; p++) {
        float lo, hi;
        upk2(z[p], lo, hi);
        zz[2 * p]     = fmaxf(lo, 0.0f);
        zz[2 * p + 1] = fmaxf(hi, 0.0f);
    }

    // ---- Scatter to the three concatenated output blocks ----
    float4* ov = reinterpret_cast<float4*>(out);
    long Ef4_b1 = 2L * (long)E;
    long Ef4_b2 = 4L * (long)E;

    ov[2 * e]              = make_float4(zz[0],  zz[1],  zz[2],  zz[3]);
    ov[2 * e + 1]          = make_float4(zz[4],  zz[5],  zz[6],  zz[7]);
    ov[Ef4_b1 + 2 * e]     = make_float4(zz[8],  zz[9],  zz[10], zz[11]);
    ov[Ef4_b1 + 2 * e + 1] = make_float4(zz[12], zz[13], zz[14], zz[15]);
    ov[Ef4_b2 + e]         = make_float4(zz[16], zz[17], zz[18], zz[19]);
}

extern "C" void kernel_launch(void* const* d_in, const int* in_sizes, int n_in,
                              void* d_out, int out_size)
{
    const float* r          = (const float*)d_in[0];
    const float* a_data     = (const float*)d_in[1];
    const float* a_material = (const float*)d_in[2];
    const float* a_influx   = (const float*)d_in[3];
    const float* b_data     = (const float*)d_in[4];
    const float* b_material = (const float*)d_in[5];
    const float* b_influx   = (const float*)d_in[6];
    const float* e_data     = (const float*)d_in[7];
    const float* W1         = (const float*)d_in[8];
    const float* b1         = (const float*)d_in[9];
    const float* W2         = (const float*)d_in[10];
    const float* b2         = (const float*)d_in[11];
    float* out = (float*)d_out;

    int E = in_sizes[0];
    int threads = 128;
    int blocks = (E + threads - 1) / threads;

    edge_mlp_kernel<<<blocks, threads>>>(r, a_data, a_material, a_influx,
                                         b_data, b_material, b_influx, e_data,
                                         W1, b1, W2, b2, out, E);
}

// round 5
// speedup vs baseline: 1.5628x; 1.5628x over previous
#include <cuda_runtime.h>
#include <cstdint>

#define NUM_IN 25   // 2*(8+2)+4+1
#define NUM_OUT 20  // 2*8+4
#define J_PAIRS 13  // 25 layer-1 rows -> 13 f32x2 pairs (last hi lane padded 0)
#define I_PAIRS 10  // 20 layer-2 rows -> 10 pairs exactly

typedef unsigned long long u64;

// Packed weights: all pairs are {W[2p][k], W[2p+1][k]} (j-adjacent, k-major).
// w1 rows padded to 14 u64 so each row is 16B-aligned (vectorizable loads).
struct __align__(16) CParams {
    u64 w1[25][14];  // [k][jp], jp<13 real
    u64 b1[14];
    u64 w2[25][10];  // [k][ip]
    u64 b2[10];
};
__constant__ CParams cP;
__device__ CParams dScratch;

__device__ __forceinline__ u64 dpack(float lo, float hi) {
    return (u64)__float_as_uint(lo) | ((u64)__float_as_uint(hi) << 32);
}
__device__ __forceinline__ u64 pk2s(float v) {   // splat {v, v}
    u64 r;
    asm("mov.b64 %0, {%1, %1};" : "=l"(r) : "f"(v));
    return r;
}
__device__ __forceinline__ void upk2(u64 v, float& lo, float& hi) {
    asm("mov.b64 {%0, %1}, %2;" : "=f"(lo), "=f"(hi) : "l"(v));
}
__device__ __forceinline__ u64 ffma2(u64 a, u64 b, u64 c) {
    u64 d;
    asm("fma.rn.f32x2 %0, %1, %2, %3;" : "=l"(d) : "l"(a), "l"(b), "l"(c));
    return d;
}

// ---- Prep: pack weights (transposed, j-paired) into dScratch ----
__global__ void prep_kernel(const float* __restrict__ W1, const float* __restrict__ b1,
                            const float* __restrict__ W2, const float* __restrict__ b2)
{
    int t = threadIdx.x;
    for (int i = t; i < 25 * 14; i += blockDim.x) {
        int k = i / 14, jp = i % 14;
        float lo = 0.0f, hi = 0.0f;
        if (jp < J_PAIRS) {
            lo = W1[(2 * jp) * NUM_IN + k];
            if (2 * jp + 1 < NUM_IN) hi = W1[(2 * jp + 1) * NUM_IN + k];
        }
        dScratch.w1[k][jp] = dpack(lo, hi);
    }
    for (int i = t; i < 14; i += blockDim.x) {
        float lo = 0.0f, hi = 0.0f;
        if (i < J_PAIRS) {
            lo = b1[2 * i];
            if (2 * i + 1 < NUM_IN) hi = b1[2 * i + 1];
        }
        dScratch.b1[i] = dpack(lo, hi);
    }
    for (int i = t; i < 25 * 10; i += blockDim.x) {
        int k = i / 10, ip = i % 10;
        dScratch.w2[k][ip] = dpack(W2[(2 * ip) * NUM_IN + k], W2[(2 * ip + 1) * NUM_IN + k]);
    }
    for (int i = t; i < 10; i += blockDim.x)
        dScratch.b2[i] = dpack(b2[2 * i], b2[2 * i + 1]);
}

// ---- Main: 2 edges/thread, weights from constant bank, no shared memory ----
__global__ void __launch_bounds__(128, 3)
edge_mlp_kernel(const float* __restrict__ r,
                const float* __restrict__ a_data,
                const float* __restrict__ a_material,
                const float* __restrict__ a_influx,
                const float* __restrict__ b_data,
                const float* __restrict__ b_material,
                const float* __restrict__ b_influx,
                const float* __restrict__ e_data,
                float* __restrict__ out,
                int E)
{
    long pair = (long)blockIdx.x * blockDim.x + threadIdx.x;
    long e0 = pair * 2;
    if (e0 >= E) return;
    bool have_e1 = (e0 + 1 < E);
    long e1 = have_e1 ? (e0 + 1) : e0;

    // ---- Gather inputs for both edges ----
    const float4* ad4 = reinterpret_cast<const float4*>(a_data);
    const float4* bd4 = reinterpret_cast<const float4*>(b_data);
    const float4* ed4 = reinterpret_cast<const float4*>(e_data);

    float x0[NUM_IN], x1[NUM_IN];
    x0[0] = r[e0]; x1[0] = r[e1];
    {
        float4 p = ad4[2 * e0], q = ad4[2 * e1];
        x0[1] = p.x; x0[2] = p.y; x0[3] = p.z; x0[4] = p.w;
        x1[1] = q.x; x1[2] = q.y; x1[3] = q.z; x1[4] = q.w;
        p = ad4[2 * e0 + 1]; q = ad4[2 * e1 + 1];
        x0[5] = p.x; x0[6] = p.y; x0[7] = p.z; x0[8] = p.w;
        x1[5] = q.x; x1[6] = q.y; x1[7] = q.z; x1[8] = q.w;
    }
    x0[9]  = a_material[e0]; x1[9]  = a_material[e1];
    x0[10] = a_influx[e0];   x1[10] = a_influx[e1];
    {
        float4 p = bd4[2 * e0], q = bd4[2 * e1];
        x0[11] = p.x; x0[12] = p.y; x0[13] = p.z; x0[14] = p.w;
        x1[11] = q.x; x1[12] = q.y; x1[13] = q.z; x1[14] = q.w;
        p = bd4[2 * e0 + 1]; q = bd4[2 * e1 + 1];
        x0[15] = p.x; x0[16] = p.y; x0[17] = p.z; x0[18] = p.w;
        x1[15] = q.x; x1[16] = q.y; x1[17] = q.z; x1[18] = q.w;
    }
    x0[19] = b_material[e0]; x1[19] = b_material[e1];
    x0[20] = b_influx[e0];   x1[20] = b_influx[e1];
    {
        float4 p = ed4[e0], q = ed4[e1];
        x0[21] = p.x; x0[22] = p.y; x0[23] = p.z; x0[24] = p.w;
        x1[21] = q.x; x1[22] = q.y; x1[23] = q.z; x1[24] = q.w;
    }

    // ---- Layer 1: j-pair accumulators, constant-bank weights feed both edges ----
    u64 acc0[J_PAIRS], acc1[J_PAIRS];
    #pragma unroll
    for (int p = 0; p < J_PAIRS; p++) { acc0[p] = cP.b1[p]; acc1[p] = cP.b1[p]; }

    #pragma unroll
    for (int k = 0; k < NUM_IN; k++) {
        u64 xk0 = pk2s(x0[k]);
        u64 xk1 = pk2s(x1[k]);
        #pragma unroll
        for (int p = 0; p < J_PAIRS; p++) {
            u64 w = cP.w1[k][p];
            acc0[p] = ffma2(w, xk0, acc0[p]);
            acc1[p] = ffma2(w, xk1, acc1[p]);
        }
    }

    float y0[2 * J_PAIRS], y1[2 * J_PAIRS];
    #pragma unroll
    for (int p = 0; p < J_PAIRS; p++) {
        float lo, hi;
        upk2(acc0[p], lo, hi);
        y0[2 * p]     = fmaxf(lo, 0.0f);
        y0[2 * p + 1] = fmaxf(hi, 0.0f);
        upk2(acc1[p], lo, hi);
        y1[2 * p]     = fmaxf(lo, 0.0f);
        y1[2 * p + 1] = fmaxf(hi, 0.0f);
    }

    // ---- Layer 2 ----
    u64 z0[I_PAIRS], z1[I_PAIRS];
    #pragma unroll
    for (int p = 0; p < I_PAIRS; p++) { z0[p] = cP.b2[p]; z1[p] = cP.b2[p]; }

    #pragma unroll
    for (int k = 0; k < NUM_IN; k++) {
        u64 yk0 = pk2s(y0[k]);
        u64 yk1 = pk2s(y1[k]);
        #pragma unroll
        for (int p = 0; p < I_PAIRS; p++) {
            u64 w = cP.w2[k][p];
            z0[p] = ffma2(w, yk0, z0[p]);
            z1[p] = ffma2(w, yk1, z1[p]);
        }
    }

    float zl[NUM_OUT], zh[NUM_OUT];
    #pragma unroll
    for (int p = 0; p < I_PAIRS; p++) {
        float lo, hi;
        upk2(z0[p], lo, hi);
        zl[2 * p]     = fmaxf(lo, 0.0f);
        zl[2 * p + 1] = fmaxf(hi, 0.0f);
        upk2(z1[p], lo, hi);
        zh[2 * p]     = fmaxf(lo, 0.0f);
        zh[2 * p + 1] = fmaxf(hi, 0.0f);
    }

    // ---- Scatter to the three concatenated output blocks ----
    float4* ov = reinterpret_cast<float4*>(out);
    long Ef4_b1 = 2L * (long)E;
    long Ef4_b2 = 4L * (long)E;

    ov[2 * e0]              = make_float4(zl[0],  zl[1],  zl[2],  zl[3]);
    ov[2 * e0 + 1]          = make_float4(zl[4],  zl[5],  zl[6],  zl[7]);
    ov[Ef4_b1 + 2 * e0]     = make_float4(zl[8],  zl[9],  zl[10], zl[11]);
    ov[Ef4_b1 + 2 * e0 + 1] = make_float4(zl[12], zl[13], zl[14], zl[15]);
    ov[Ef4_b2 + e0]         = make_float4(zl[16], zl[17], zl[18], zl[19]);

    if (have_e1) {
        ov[2 * e1]              = make_float4(zh[0],  zh[1],  zh[2],  zh[3]);
        ov[2 * e1 + 1]          = make_float4(zh[4],  zh[5],  zh[6],  zh[7]);
        ov[Ef4_b1 + 2 * e1]     = make_float4(zh[8],  zh[9],  zh[10], zh[11]);
        ov[Ef4_b1 + 2 * e1 + 1] = make_float4(zh[12], zh[13], zh[14], zh[15]);
        ov[Ef4_b2 + e1]         = make_float4(zh[16], zh[17], zh[18], zh[19]);
    }
}

extern "C" void kernel_launch(void* const* d_in, const int* in_sizes, int n_in,
                              void* d_out, int out_size)
{
    const float* r          = (const float*)d_in[0];
    const float* a_data     = (const float*)d_in[1];
    const float* a_material = (const float*)d_in[2];
    const float* a_influx   = (const float*)d_in[3];
    const float* b_data     = (const float*)d_in[4];
    const float* b_material = (const float*)d_in[5];
    const float* b_influx   = (const float*)d_in[6];
    const float* e_data     = (const float*)d_in[7];
    const float* W1         = (const float*)d_in[8];
    const float* b1         = (const float*)d_in[9];
    const float* W2         = (const float*)d_in[10];
    const float* b2         = (const float*)d_in[11];
    float* out = (float*)d_out;

    int E = in_sizes[0];

    // 1) Pack weights into __device__ scratch (transposed, j-paired).
    prep_kernel<<<1, 256>>>(W1, b1, W2, b2);

    // 2) D2D copy scratch -> __constant__ symbol (graph-capturable memcpy node).
    void* cp_addr = nullptr;
    void* scr_addr = nullptr;
    cudaGetSymbolAddress(&cp_addr, cP);
    cudaGetSymbolAddress(&scr_addr, dScratch);
    cudaMemcpyAsync(cp_addr, scr_addr, sizeof(CParams), cudaMemcpyDeviceToDevice, 0);

    // 3) Main kernel: 2 edges per thread.
    long pairs = ((long)E + 1) / 2;
    int threads = 128;
    int blocks = (int)((pairs + threads - 1) / threads);
    edge_mlp_kernel<<<blocks, threads>>>(r, a_data, a_material, a_influx,
                                         b_data, b_material, b_influx, e_data,
                                         out, E);
}

// round 6
// speedup vs baseline: 1.5712x; 1.0054x over previous
#include <cuda_runtime.h>
#include <cstdint>

#define NUM_IN 25   // 2*(8+2)+4+1
#define NUM_OUT 20  // 2*8+4
#define J_PAIRS 13  // 25 layer-1 rows -> 13 f32x2 pairs (last hi lane padded 0)
#define I_PAIRS 10  // 20 layer-2 rows -> 10 pairs exactly

typedef unsigned long long u64;

// Packed weights: all pairs are {W[2p][k], W[2p+1][k]} (j-adjacent, k-major).
// w1 rows padded to 14 u64 so each row is 16B-aligned (112B row stride).
struct __align__(16) CParams {
    u64 w1[25][14];  // [k][jp], jp<13 real, jp=13 zero
    u64 b1[14];
    u64 w2[25][10];  // [k][ip]
    u64 b2[10];
};
__constant__ CParams cP;
__device__ CParams dScratch;

__device__ __forceinline__ u64 dpack(float lo, float hi) {
    return (u64)__float_as_uint(lo) | ((u64)__float_as_uint(hi) << 32);
}
__device__ __forceinline__ u64 pk2s(float v) {   // splat {v, v}
    u64 r;
    asm("mov.b64 %0, {%1, %1};" : "=l"(r) : "f"(v));
    return r;
}
__device__ __forceinline__ void upk2(u64 v, float& lo, float& hi) {
    asm("mov.b64 {%0, %1}, %2;" : "=f"(lo), "=f"(hi) : "l"(v));
}
__device__ __forceinline__ u64 ffma2(u64 a, u64 b, u64 c) {
    u64 d;
    asm("fma.rn.f32x2 %0, %1, %2, %3;" : "=l"(d) : "l"(a), "l"(b), "l"(c));
    return d;
}

// ---- Prep: pack weights (transposed, j-paired) into dScratch ----
__global__ void prep_kernel(const float* __restrict__ W1, const float* __restrict__ b1,
                            const float* __restrict__ W2, const float* __restrict__ b2)
{
    int t = blockIdx.x * blockDim.x + threadIdx.x;
    int stride = gridDim.x * blockDim.x;
    for (int i = t; i < 25 * 14; i += stride) {
        int k = i / 14, jp = i % 14;
        float lo = 0.0f, hi = 0.0f;
        if (jp < J_PAIRS) {
            lo = W1[(2 * jp) * NUM_IN + k];
            if (2 * jp + 1 < NUM_IN) hi = W1[(2 * jp + 1) * NUM_IN + k];
        }
        dScratch.w1[k][jp] = dpack(lo, hi);
    }
    for (int i = t; i < 14; i += stride) {
        float lo = 0.0f, hi = 0.0f;
        if (i < J_PAIRS) {
            lo = b1[2 * i];
            if (2 * i + 1 < NUM_IN) hi = b1[2 * i + 1];
        }
        dScratch.b1[i] = dpack(lo, hi);
    }
    for (int i = t; i < 25 * 10; i += stride) {
        int k = i / 10, ip = i % 10;
        dScratch.w2[k][ip] = dpack(W2[(2 * ip) * NUM_IN + k], W2[(2 * ip + 1) * NUM_IN + k]);
    }
    for (int i = t; i < 10; i += stride)
        dScratch.b2[i] = dpack(b2[2 * i], b2[2 * i + 1]);
}

// ---- Main: 2 edges/thread, constant-bank weights (v2.u64 loads), no smem ----
__global__ void __launch_bounds__(128, 4)
edge_mlp_kernel(const float* __restrict__ r,
                const float* __restrict__ a_data,
                const float* __restrict__ a_material,
                const float* __restrict__ a_influx,
                const float* __restrict__ b_data,
                const float* __restrict__ b_material,
                const float* __restrict__ b_influx,
                const float* __restrict__ e_data,
                float* __restrict__ out,
                int E)
{
    long pair = (long)blockIdx.x * blockDim.x + threadIdx.x;
    long e0 = pair * 2;
    if (e0 >= E) return;
    bool have_e1 = (e0 + 1 < E);
    long e1 = have_e1 ? (e0 + 1) : e0;

    // ---- Gather inputs for both edges ----
    const float4* ad4 = reinterpret_cast<const float4*>(a_data);
    const float4* bd4 = reinterpret_cast<const float4*>(b_data);
    const float4* ed4 = reinterpret_cast<const float4*>(e_data);

    float x0[NUM_IN], x1[NUM_IN];
    x0[0] = r[e0]; x1[0] = r[e1];
    {
        float4 p = ad4[2 * e0], q = ad4[2 * e1];
        x0[1] = p.x; x0[2] = p.y; x0[3] = p.z; x0[4] = p.w;
        x1[1] = q.x; x1[2] = q.y; x1[3] = q.z; x1[4] = q.w;
        p = ad4[2 * e0 + 1]; q = ad4[2 * e1 + 1];
        x0[5] = p.x; x0[6] = p.y; x0[7] = p.z; x0[8] = p.w;
        x1[5] = q.x; x1[6] = q.y; x1[7] = q.z; x1[8] = q.w;
    }
    x0[9]  = a_material[e0]; x1[9]  = a_material[e1];
    x0[10] = a_influx[e0];   x1[10] = a_influx[e1];
    {
        float4 p = bd4[2 * e0], q = bd4[2 * e1];
        x0[11] = p.x; x0[12] = p.y; x0[13] = p.z; x0[14] = p.w;
        x1[11] = q.x; x1[12] = q.y; x1[13] = q.z; x1[14] = q.w;
        p = bd4[2 * e0 + 1]; q = bd4[2 * e1 + 1];
        x0[15] = p.x; x0[16] = p.y; x0[17] = p.z; x0[18] = p.w;
        x1[15] = q.x; x1[16] = q.y; x1[17] = q.z; x1[18] = q.w;
    }
    x0[19] = b_material[e0]; x1[19] = b_material[e1];
    x0[20] = b_influx[e0];   x1[20] = b_influx[e1];
    {
        float4 p = ed4[e0], q = ed4[e1];
        x0[21] = p.x; x0[22] = p.y; x0[23] = p.z; x0[24] = p.w;
        x1[21] = q.x; x1[22] = q.y; x1[23] = q.z; x1[24] = q.w;
    }

    // ---- Layer 1: j-pair accumulators; vector const loads feed both edges ----
    u64 acc0[J_PAIRS], acc1[J_PAIRS];
    {
        const ulonglong2* bv = reinterpret_cast<const ulonglong2*>(cP.b1);
        #pragma unroll
        for (int q = 0; q < 6; q++) {
            ulonglong2 b = bv[q];
            acc0[2 * q] = b.x; acc1[2 * q] = b.x;
            acc0[2 * q + 1] = b.y; acc1[2 * q + 1] = b.y;
        }
        acc0[12] = cP.b1[12]; acc1[12] = cP.b1[12];
    }

    #pragma unroll
    for (int k = 0; k < NUM_IN; k++) {
        u64 xk0 = pk2s(x0[k]);
        u64 xk1 = pk2s(x1[k]);
        const ulonglong2* wv = reinterpret_cast<const ulonglong2*>(cP.w1[k]);
        #pragma unroll
        for (int q = 0; q < 6; q++) {
            ulonglong2 w = wv[q];
            acc0[2 * q]     = ffma2(w.x, xk0, acc0[2 * q]);
            acc1[2 * q]     = ffma2(w.x, xk1, acc1[2 * q]);
            acc0[2 * q + 1] = ffma2(w.y, xk0, acc0[2 * q + 1]);
            acc1[2 * q + 1] = ffma2(w.y, xk1, acc1[2 * q + 1]);
        }
        u64 w12 = cP.w1[k][12];
        acc0[12] = ffma2(w12, xk0, acc0[12]);
        acc1[12] = ffma2(w12, xk1, acc1[12]);
    }

    float y0[2 * J_PAIRS], y1[2 * J_PAIRS];
    #pragma unroll
    for (int p = 0; p < J_PAIRS; p++) {
        float lo, hi;
        upk2(acc0[p], lo, hi);
        y0[2 * p]     = fmaxf(lo, 0.0f);
        y0[2 * p + 1] = fmaxf(hi, 0.0f);
        upk2(acc1[p], lo, hi);
        y1[2 * p]     = fmaxf(lo, 0.0f);
        y1[2 * p + 1] = fmaxf(hi, 0.0f);
    }

    // ---- Layer 2: 10 pairs, vector const loads ----
    u64 z0[I_PAIRS], z1[I_PAIRS];
    {
        const ulonglong2* bv = reinterpret_cast<const ulonglong2*>(cP.b2);
        #pragma unroll
        for (int q = 0; q < 5; q++) {
            ulonglong2 b = bv[q];
            z0[2 * q] = b.x; z1[2 * q] = b.x;
            z0[2 * q + 1] = b.y; z1[2 * q + 1] = b.y;
        }
    }

    #pragma unroll
    for (int k = 0; k < NUM_IN; k++) {
        u64 yk0 = pk2s(y0[k]);
        u64 yk1 = pk2s(y1[k]);
        const ulonglong2* wv = reinterpret_cast<const ulonglong2*>(cP.w2[k]);
        #pragma unroll
        for (int q = 0; q < 5; q++) {
            ulonglong2 w = wv[q];
            z0[2 * q]     = ffma2(w.x, yk0, z0[2 * q]);
            z1[2 * q]     = ffma2(w.x, yk1, z1[2 * q]);
            z0[2 * q + 1] = ffma2(w.y, yk0, z0[2 * q + 1]);
            z1[2 * q + 1] = ffma2(w.y, yk1, z1[2 * q + 1]);
        }
    }

    float zl[NUM_OUT], zh[NUM_OUT];
    #pragma unroll
    for (int p = 0; p < I_PAIRS; p++) {
        float lo, hi;
        upk2(z0[p], lo, hi);
        zl[2 * p]     = fmaxf(lo, 0.0f);
        zl[2 * p + 1] = fmaxf(hi, 0.0f);
        upk2(z1[p], lo, hi);
        zh[2 * p]     = fmaxf(lo, 0.0f);
        zh[2 * p + 1] = fmaxf(hi, 0.0f);
    }

    // ---- Scatter to the three concatenated output blocks ----
    float4* ov = reinterpret_cast<float4*>(out);
    long Ef4_b1 = 2L * (long)E;
    long Ef4_b2 = 4L * (long)E;

    ov[2 * e0]              = make_float4(zl[0],  zl[1],  zl[2],  zl[3]);
    ov[2 * e0 + 1]          = make_float4(zl[4],  zl[5],  zl[6],  zl[7]);
    ov[Ef4_b1 + 2 * e0]     = make_float4(zl[8],  zl[9],  zl[10], zl[11]);
    ov[Ef4_b1 + 2 * e0 + 1] = make_float4(zl[12], zl[13], zl[14], zl[15]);
    ov[Ef4_b2 + e0]         = make_float4(zl[16], zl[17], zl[18], zl[19]);

    if (have_e1) {
        ov[2 * e1]              = make_float4(zh[0],  zh[1],  zh[2],  zh[3]);
        ov[2 * e1 + 1]          = make_float4(zh[4],  zh[5],  zh[6],  zh[7]);
        ov[Ef4_b1 + 2 * e1]     = make_float4(zh[8],  zh[9],  zh[10], zh[11]);
        ov[Ef4_b1 + 2 * e1 + 1] = make_float4(zh[12], zh[13], zh[14], zh[15]);
        ov[Ef4_b2 + e1]         = make_float4(zh[16], zh[17], zh[18], zh[19]);
    }
}

extern "C" void kernel_launch(void* const* d_in, const int* in_sizes, int n_in,
                              void* d_out, int out_size)
{
    const float* r          = (const float*)d_in[0];
    const float* a_data     = (const float*)d_in[1];
    const float* a_material = (const float*)d_in[2];
    const float* a_influx   = (const float*)d_in[3];
    const float* b_data     = (const float*)d_in[4];
    const float* b_material = (const float*)d_in[5];
    const float* b_influx   = (const float*)d_in[6];
    const float* e_data     = (const float*)d_in[7];
    const float* W1         = (const float*)d_in[8];
    const float* b1         = (const float*)d_in[9];
    const float* W2         = (const float*)d_in[10];
    const float* b2         = (const float*)d_in[11];
    float* out = (float*)d_out;

    int E = in_sizes[0];

    // 1) Pack weights into __device__ scratch (transposed, j-paired).
    prep_kernel<<<8, 128>>>(W1, b1, W2, b2);

    // 2) D2D copy scratch -> __constant__ symbol (graph-capturable memcpy node).
    void* cp_addr = nullptr;
    void* scr_addr = nullptr;
    cudaGetSymbolAddress(&cp_addr, cP);
    cudaGetSymbolAddress(&scr_addr, dScratch);
    cudaMemcpyAsync(cp_addr, scr_addr, sizeof(CParams), cudaMemcpyDeviceToDevice, 0);

    // 3) Main kernel: 2 edges per thread.
    long pairs = ((long)E + 1) / 2;
    int threads = 128;
    int blocks = (int)((pairs + threads - 1) / threads);
    edge_mlp_kernel<<<blocks, threads>>>(r, a_data, a_material, a_influx,
                                         b_data, b_material, b_influx, e_data,
                                         out, E);
}